// round 8
// baseline (speedup 1.0000x reference)
#include <cuda_runtime.h>
#include <cuda_bf16.h>
#include <cstdint>

// ---------------------------------------------------------------------------
// Fused Gaussian rasterizer, R8:
//  - 16x16 px tiles, 256 CTAs x 256 threads, 2 gaussians/thread projection
//  - rank-scatter depth sort (records in depth order in smem)
//  - NEW: 4 warps build 8x8-quadrant u16 index sub-lists (order-preserving),
//    each warp composites one 8x4 pixel patch -> warp-uniform sub-list walk,
//    ~27% fewer masked iterations, coherent early-out
//  - opacity folded into exp2 bias; batch-4 pipelined EX2
// ---------------------------------------------------------------------------

#define NG    512
#define IMG   256
#define TW    16
#define TH    16
#define NT    256
#define NWARP (NT/32)

__device__ __forceinline__ float ex2(float x) {
    float y;
    asm("ex2.approx.ftz.f32 %0, %1;" : "=f"(y) : "f"(x));
    return y;
}

__global__ __launch_bounds__(NT)
void gs_fused(const float* __restrict__ pos,
              const float* __restrict__ cov3d,
              const float* __restrict__ opac,
              const float* __restrict__ cols,
              const float* __restrict__ Km,
              const float* __restrict__ Rm,
              const float* __restrict__ tv,
              float* __restrict__ out)
{
    __shared__ float4             rec[NG + 4][3];  // ~24.2 KB, + dummy slots
    __shared__ unsigned long long skey[NG];        // 4 KB; reused as qidx
    __shared__ uint2              bbq[NG];         // 4 KB packed bboxes
    __shared__ int                warpTotals[NWARP];
    __shared__ int                qcnt[4];

    unsigned short* qidx = (unsigned short*)skey;  // [4][512] u16, aliases skey

    const int tid  = threadIdx.x;
    const int lane = tid & 31;
    const int wid  = tid >> 5;

    const int tileX = blockIdx.x * TW;
    const int tileY = blockIdx.y * TH;
    const float tX0 = (float)tileX, tX1 = (float)(tileX + TW);
    const float tY0 = (float)tileY, tY1 = (float)(tileY + TH);

    const float r00 = Rm[0], r01 = Rm[1], r02 = Rm[2];
    const float r10 = Rm[3], r11 = Rm[4], r12 = Rm[5];
    const float r20 = Rm[6], r21 = Rm[7], r22 = Rm[8];
    const float fx  = Km[0], fy = Km[4];

    // ---------------- phase 1: project 2 gaussians/thread ----------------
    bool  flg[2];
    unsigned long long key[2];
    float Fmx[2], Fmy[2], Fe00[2], Fe01[2], Fe11[2], Fbias[2];
    float Fcr[2], Fcg[2], Fcb[2];
    unsigned Flo[2], Fhi[2];

    #pragma unroll
    for (int s = 0; s < 2; s++) {
        const int g = tid + s * NT;
        const float p0 = pos[3*g+0], p1 = pos[3*g+1], p2 = pos[3*g+2];

        const float cam0 = r00*p0 + r01*p1 + r02*p2 + tv[0];
        const float cam1 = r10*p0 + r11*p1 + r12*p2 + tv[1];
        const float cam2 = r20*p0 + r21*p1 + r22*p2 + tv[2];

        const float pr0 = Km[0]*cam0 + Km[1]*cam1 + Km[2]*cam2;
        const float pr1 = Km[3]*cam0 + Km[4]*cam1 + Km[5]*cam2;
        const float pr2 = Km[6]*cam0 + Km[7]*cam1 + Km[8]*cam2;
        const float rz = 1.0f / pr2;
        const float mx = pr0 * rz;
        const float my = pr1 * rz;

        const float z   = cam2;
        const float iz  = 1.0f / z;
        const float jx0 = fx * iz;
        const float jx2 = -fx * cam0 * iz * iz;
        const float jy1 = fy * iz;
        const float jy2 = -fy * cam1 * iz * iz;

        // P = J * R  (2x3)
        const float P00 = jx0*r00 + jx2*r20;
        const float P01 = jx0*r01 + jx2*r21;
        const float P02 = jx0*r02 + jx2*r22;
        const float P10 = jy1*r10 + jy2*r20;
        const float P11 = jy1*r11 + jy2*r21;
        const float P12 = jy1*r12 + jy2*r22;

        const float c00 = cov3d[9*g+0];
        const float c01 = cov3d[9*g+1];
        const float c02 = cov3d[9*g+2];
        const float c11 = cov3d[9*g+4];
        const float c12 = cov3d[9*g+5];
        const float c22 = cov3d[9*g+8];

        const float t00 = c00*P00 + c01*P01 + c02*P02;
        const float t01 = c01*P00 + c11*P01 + c12*P02;
        const float t02 = c02*P00 + c12*P01 + c22*P02;
        const float t10 = c00*P10 + c01*P11 + c02*P12;
        const float t11 = c01*P10 + c11*P11 + c12*P12;
        const float t12 = c02*P10 + c12*P11 + c22*P12;

        const float a = P00*t00 + P01*t01 + P02*t02 + 0.3f;
        const float b = P10*t00 + P11*t01 + P12*t02;
        const float c = P10*t10 + P11*t11 + P12*t12 + 0.3f;

        const float det  = fmaxf(a*c - b*b, 1e-8f);
        const float idet = 1.0f / det;
        // exp2 prescale: exp(-0.5*m) = exp2(-0.72134752*m)
        Fe00[s] = -0.72134752f * c * idet;
        Fe01[s] =  1.44269504f * b * idet;
        Fe11[s] = -0.72134752f * a * idet;

        const float hd = (a - c) * 0.5f;
        const float max_eig = (a + c)*0.5f + sqrtf(fmaxf(hd*hd + b*b, 1e-8f));
        const float radius = 3.0f * sqrtf(max_eig);

        const float x_min = fmaxf(0.0f,       truncf(mx - radius));
        const float x_max = fminf((float)IMG, truncf(mx + radius) + 1.0f);
        const float y_min = fmaxf(0.0f,       truncf(my - radius));
        const float y_max = fminf((float)IMG, truncf(my + radius) + 1.0f);

        flg[s] = (x_min < tX1) && (x_max > tX0) &&
                 (y_min < tY1) && (y_max > tY0);
        key[s] = ((unsigned long long)__float_as_uint(z) << 16)
               | (unsigned long long)g;

        Fmx[s] = mx;  Fmy[s] = my;
        Fbias[s] = __log2f(opac[g]);
        Fcr[s] = cols[3*g+0];  Fcg[s] = cols[3*g+1];  Fcb[s] = cols[3*g+2];
        Flo[s] = (unsigned)x_min | ((unsigned)x_max << 16);
        Fhi[s] = (unsigned)y_min | ((unsigned)y_max << 16);
    }

    // ---------------- phase 2: compaction slots ----------------
    const unsigned m0 = __ballot_sync(0xffffffffu, flg[0]);
    const unsigned m1 = __ballot_sync(0xffffffffu, flg[1]);
    if (lane == 0) warpTotals[wid] = __popc(m0) | (__popc(m1) << 16);
    __syncthreads();

    int prefix = 0, total = 0;
    #pragma unroll
    for (int w = 0; w < NWARP; w++) {
        const int t = warpTotals[w];
        if (w < wid) prefix += t;
        total += t;
    }
    const int count0 = total & 0xffff;
    const int count  = count0 + (total >> 16);
    const unsigned lm = (1u << lane) - 1u;
    const int pos0 = (prefix & 0xffff) + __popc(m0 & lm);
    const int pos1 = count0 + (prefix >> 16) + __popc(m1 & lm);

    if (flg[0]) skey[pos0] = key[0];
    if (flg[1]) skey[pos1] = key[1];
    __syncthreads();

    // ---------------- phase 3: rank ----------------
    int rank0 = 0, rank1 = 0;
    if (flg[0] | flg[1]) {
        for (int j = 0; j < count; j++) {
            const unsigned long long kj = skey[j];
            rank0 += (kj < key[0]);
            rank1 += (kj < key[1]);
        }
    }
    __syncthreads();   // all skey reads done (qidx aliases it later)

    // ---------------- phase 3b: scatter records + bboxes ----------------
    if (flg[0]) {
        rec[rank0][0] = make_float4(Fmx[0], Fmy[0], Fe00[0], Fe01[0]);
        rec[rank0][1] = make_float4(Fe11[0], Fbias[0], Fcr[0], Fcg[0]);
        rec[rank0][2] = make_float4(Fcb[0], __uint_as_float(Flo[0]),
                                    __uint_as_float(Fhi[0]), 0.f);
        bbq[rank0] = make_uint2(Flo[0], Fhi[0]);
    }
    if (flg[1]) {
        rec[rank1][0] = make_float4(Fmx[1], Fmy[1], Fe00[1], Fe01[1]);
        rec[rank1][1] = make_float4(Fe11[1], Fbias[1], Fcr[1], Fcg[1]);
        rec[rank1][2] = make_float4(Fcb[1], __uint_as_float(Flo[1]),
                                    __uint_as_float(Fhi[1]), 0.f);
        bbq[rank1] = make_uint2(Flo[1], Fhi[1]);
    }
    // 4 never-inside dummy records right after the list (for sub-list padding)
    if (tid < 4) {
        rec[count + tid][0] = make_float4(0.f, 0.f, 0.f, 0.f);
        rec[count + tid][1] = make_float4(0.f, 0.f, 0.f, 0.f);
        rec[count + tid][2] = make_float4(0.f, __uint_as_float(0xFFFFu),
                                          __uint_as_float(0xFFFFu), 0.f);
    }
    __syncthreads();

    // ---------------- phase 4: build quadrant sub-lists (warps 0-3) ------
    if (wid < 4) {
        const int q   = wid;
        const int qx0 = tileX + ((q & 1) << 3);
        const int qy0 = tileY + ((q >> 1) << 3);
        const int qx1 = qx0 + 8, qy1 = qy0 + 8;

        int qn = 0;
        for (int j0 = 0; j0 < count; j0 += 32) {
            const int j = j0 + lane;
            bool f = false;
            if (j < count) {
                const uint2 bb = bbq[j];
                const int x0 = (int)(bb.x & 0xffffu), x1 = (int)(bb.x >> 16);
                const int y0 = (int)(bb.y & 0xffffu), y1 = (int)(bb.y >> 16);
                f = (x0 < qx1) & (x1 > qx0) & (y0 < qy1) & (y1 > qy0);
            }
            const unsigned mm = __ballot_sync(0xffffffffu, f);
            if (f) qidx[(q << 9) + qn + __popc(mm & lm)] = (unsigned short)j;
            qn += __popc(mm);
        }
        const int qnP = (qn + 3) & ~3;
        if (lane < qnP - qn)
            qidx[(q << 9) + qn + lane] = (unsigned short)(count + lane);
        if (lane == 0) qcnt[q] = qnP;
    }
    __syncthreads();

    // ---------------- phase 5: composite (warp = 8x4 patch of quadrant) --
    const int q   = wid >> 1;
    const int pxi = tileX + ((q & 1) << 3) + (lane & 7);
    const int pyi = tileY + ((q >> 1) << 3) + ((wid & 1) << 2) + (lane >> 3);
    const float pxf = (float)pxi;
    const float pyf = (float)pyi;
    const int qn = qcnt[q];
    const unsigned short* ql = qidx + (q << 9);

    float T = 1.0f, rr = 0.0f, gg = 0.0f, bb = 0.0f;
    for (int base = 0; base < qn; base += 4) {
        int id[4];
        float4 q0[4], q1[4], q2[4];
        #pragma unroll
        for (int i = 0; i < 4; i++) id[i] = ql[base + i];
        #pragma unroll
        for (int i = 0; i < 4; i++) {
            q0[i] = rec[id[i]][0];
            q1[i] = rec[id[i]][1];
            q2[i] = rec[id[i]][2];
        }
        float gs[4];
        #pragma unroll
        for (int i = 0; i < 4; i++) {
            const unsigned lo = __float_as_uint(q2[i].y);
            const unsigned hi = __float_as_uint(q2[i].z);
            const int x0 = (int)(lo & 0xffffu), x1 = (int)(lo >> 16);
            const int y0 = (int)(hi & 0xffffu), y1 = (int)(hi >> 16);
            const bool inb = (pxi >= x0) & (pxi < x1) & (pyi >= y0) & (pyi < y1);
            const float dx = pxf - q0[i].x;
            const float dy = pyf - q0[i].y;
            const float u  = fmaf(q1[i].x * dy, dy, q1[i].y);   // e11*dy^2 + bias
            const float pl = fmaf(q0[i].w, dy, q0[i].z * dx);   // e01*dy + e00*dx
            const float e  = fmaf(pl, dx, u);
            gs[i] = inb ? ex2(e) : 0.0f;                        // alpha
        }
        #pragma unroll
        for (int i = 0; i < 4; i++) {
            const float tg = T * gs[i];
            rr = fmaf(tg, q1[i].z, rr);
            gg = fmaf(tg, q1[i].w, gg);
            bb = fmaf(tg, q2[i].x, bb);
            T  = T - tg;
        }
        if (T < 1e-5f) break;
    }

    const int idx = (pyi * IMG + pxi) * 3;
    out[idx + 0] = rr;
    out[idx + 1] = gg;
    out[idx + 2] = bb;
}

extern "C" void kernel_launch(void* const* d_in, const int* in_sizes, int n_in,
                              void* d_out, int out_size)
{
    const float* pos   = (const float*)d_in[0];  // (512,3)
    const float* cov3d = (const float*)d_in[1];  // (512,3,3)
    const float* opac  = (const float*)d_in[2];  // (512,1)
    const float* cols  = (const float*)d_in[3];  // (512,3)
    const float* Km    = (const float*)d_in[4];  // (3,3)
    const float* Rm    = (const float*)d_in[5];  // (3,3)
    const float* tv    = (const float*)d_in[6];  // (3,)
    float* out = (float*)d_out;                  // (256,256,3)

    gs_fused<<<dim3(IMG/TW, IMG/TH), NT>>>(pos, cov3d, opac, cols, Km, Rm, tv, out);
}

// round 10
// speedup vs baseline: 2.3661x; 2.3661x over previous
#include <cuda_runtime.h>
#include <cuda_bf16.h>
#include <cstdint>

// ---------------------------------------------------------------------------
// Gaussian rasterizer, R9 (resubmit after infra failure): two kernels.
//  A: project all 512 gaussians once (4 CTAs x 128), records -> device globals
//     (L2-resident ~26KB for the raster pass).
//  B: 256 CTAs x 256 thr (16x16 tile, 1 px/thread): coalesced bbox cull,
//     rank-sort of survivors only (~34 keys), record fetch overlapped with
//     rank loop, batch-4 EX2 composite with early-out (R6 inner loop).
// ---------------------------------------------------------------------------

#define NG    512
#define IMG   256
#define TW    16
#define TH    16
#define NT    256
#define NWARP (NT/32)

__device__ float4 g_rec[NG][3];
__device__ uint2  g_bb[NG];
__device__ float  g_z[NG];

__device__ __forceinline__ float ex2(float x) {
    float y;
    asm("ex2.approx.ftz.f32 %0, %1;" : "=f"(y) : "f"(x));
    return y;
}

// ------------------------------ kernel A -----------------------------------
__global__ __launch_bounds__(128)
void gs_project(const float* __restrict__ pos,
                const float* __restrict__ cov3d,
                const float* __restrict__ opac,
                const float* __restrict__ cols,
                const float* __restrict__ Km,
                const float* __restrict__ Rm,
                const float* __restrict__ tv)
{
    const int g = blockIdx.x * 128 + threadIdx.x;

    const float r00 = Rm[0], r01 = Rm[1], r02 = Rm[2];
    const float r10 = Rm[3], r11 = Rm[4], r12 = Rm[5];
    const float r20 = Rm[6], r21 = Rm[7], r22 = Rm[8];
    const float fx  = Km[0], fy = Km[4];

    const float p0 = pos[3*g+0], p1 = pos[3*g+1], p2 = pos[3*g+2];

    const float cam0 = r00*p0 + r01*p1 + r02*p2 + tv[0];
    const float cam1 = r10*p0 + r11*p1 + r12*p2 + tv[1];
    const float cam2 = r20*p0 + r21*p1 + r22*p2 + tv[2];

    const float pr0 = Km[0]*cam0 + Km[1]*cam1 + Km[2]*cam2;
    const float pr1 = Km[3]*cam0 + Km[4]*cam1 + Km[5]*cam2;
    const float pr2 = Km[6]*cam0 + Km[7]*cam1 + Km[8]*cam2;
    const float rz = 1.0f / pr2;
    const float mx = pr0 * rz;
    const float my = pr1 * rz;

    const float z   = cam2;
    const float iz  = 1.0f / z;
    const float jx0 = fx * iz;
    const float jx2 = -fx * cam0 * iz * iz;
    const float jy1 = fy * iz;
    const float jy2 = -fy * cam1 * iz * iz;

    // P = J * R  (2x3)
    const float P00 = jx0*r00 + jx2*r20;
    const float P01 = jx0*r01 + jx2*r21;
    const float P02 = jx0*r02 + jx2*r22;
    const float P10 = jy1*r10 + jy2*r20;
    const float P11 = jy1*r11 + jy2*r21;
    const float P12 = jy1*r12 + jy2*r22;

    // symmetric C
    const float c00 = cov3d[9*g+0];
    const float c01 = cov3d[9*g+1];
    const float c02 = cov3d[9*g+2];
    const float c11 = cov3d[9*g+4];
    const float c12 = cov3d[9*g+5];
    const float c22 = cov3d[9*g+8];

    const float t00 = c00*P00 + c01*P01 + c02*P02;
    const float t01 = c01*P00 + c11*P01 + c12*P02;
    const float t02 = c02*P00 + c12*P01 + c22*P02;
    const float t10 = c00*P10 + c01*P11 + c02*P12;
    const float t11 = c01*P10 + c11*P11 + c12*P12;
    const float t12 = c02*P10 + c12*P11 + c22*P12;

    const float a = P00*t00 + P01*t01 + P02*t02 + 0.3f;
    const float b = P10*t00 + P11*t01 + P12*t02;
    const float c = P10*t10 + P11*t11 + P12*t12 + 0.3f;

    const float det  = fmaxf(a*c - b*b, 1e-8f);
    const float idet = 1.0f / det;
    // exp2 prescale: exp(-0.5*m) = exp2(-0.72134752*m)
    const float e00 = -0.72134752f * c * idet;
    const float e01 =  1.44269504f * b * idet;
    const float e11 = -0.72134752f * a * idet;

    const float hd = (a - c) * 0.5f;
    const float max_eig = (a + c)*0.5f + sqrtf(fmaxf(hd*hd + b*b, 1e-8f));
    const float radius = 3.0f * sqrtf(max_eig);

    const float x_min = fmaxf(0.0f,       truncf(mx - radius));
    const float x_max = fminf((float)IMG, truncf(mx + radius) + 1.0f);
    const float y_min = fmaxf(0.0f,       truncf(my - radius));
    const float y_max = fminf((float)IMG, truncf(my + radius) + 1.0f);

    const float bias = __log2f(opac[g]);
    const unsigned lo = (unsigned)x_min | ((unsigned)x_max << 16);
    const unsigned hi = (unsigned)y_min | ((unsigned)y_max << 16);

    g_rec[g][0] = make_float4(mx, my, e00, e01);
    g_rec[g][1] = make_float4(e11, bias, cols[3*g+0], cols[3*g+1]);
    g_rec[g][2] = make_float4(cols[3*g+2], __uint_as_float(lo),
                              __uint_as_float(hi), 0.f);
    g_bb[g] = make_uint2(lo, hi);
    g_z[g]  = z;
}

// ------------------------------ kernel B -----------------------------------
__global__ __launch_bounds__(NT)
void gs_raster(float* __restrict__ out)
{
    __shared__ float4             rec[NG + 4][3];  // ~24.2 KB
    __shared__ unsigned long long skey[NG];        // 4 KB
    __shared__ int                warpTotals[NWARP];

    const int tid  = threadIdx.x;
    const int lane = tid & 31;
    const int wid  = tid >> 5;

    const int tileX = blockIdx.x * TW;
    const int tileY = blockIdx.y * TH;

    // ---------------- phase 1: cull 2 gaussians/thread (loads only) ------
    bool  flg[2];
    unsigned long long key[2];
    float4 R0[2], R1[2], R2[2];

    #pragma unroll
    for (int s = 0; s < 2; s++) {
        const int g = tid + s * NT;
        const uint2 bb = g_bb[g];                       // coalesced LDG.64
        const int x0 = (int)(bb.x & 0xffffu), x1 = (int)(bb.x >> 16);
        const int y0 = (int)(bb.y & 0xffffu), y1 = (int)(bb.y >> 16);
        flg[s] = (x0 < tileX + TW) & (x1 > tileX) &
                 (y0 < tileY + TH) & (y1 > tileY);
        const float z = g_z[g];                         // coalesced LDG.32
        key[s] = ((unsigned long long)__float_as_uint(z) << 16)
               | (unsigned long long)g;
        if (flg[s]) {                                   // L2 fetch, overlaps rank
            R0[s] = g_rec[g][0];
            R1[s] = g_rec[g][1];
            R2[s] = g_rec[g][2];
        }
    }

    // ---------------- phase 2: compaction slots ----------------
    const unsigned m0 = __ballot_sync(0xffffffffu, flg[0]);
    const unsigned m1 = __ballot_sync(0xffffffffu, flg[1]);
    if (lane == 0) warpTotals[wid] = __popc(m0) | (__popc(m1) << 16);
    __syncthreads();

    int prefix = 0, total = 0;
    #pragma unroll
    for (int w = 0; w < NWARP; w++) {
        const int t = warpTotals[w];
        if (w < wid) prefix += t;
        total += t;
    }
    const int count0 = total & 0xffff;
    const int count  = count0 + (total >> 16);
    const unsigned lm = (1u << lane) - 1u;
    const int pos0 = (prefix & 0xffff) + __popc(m0 & lm);
    const int pos1 = count0 + (prefix >> 16) + __popc(m1 & lm);

    if (flg[0]) skey[pos0] = key[0];
    if (flg[1]) skey[pos1] = key[1];
    __syncthreads();

    // ---------------- phase 3: rank over survivors only ----------------
    int rank0 = 0, rank1 = 0;
    if (flg[0] | flg[1]) {
        for (int j = 0; j < count; j++) {
            const unsigned long long kj = skey[j];
            rank0 += (kj < key[0]);
            rank1 += (kj < key[1]);
        }
    }
    // scatter records into depth order (rec distinct from skey: no barrier)
    if (flg[0]) { rec[rank0][0] = R0[0]; rec[rank0][1] = R1[0]; rec[rank0][2] = R2[0]; }
    if (flg[1]) { rec[rank1][0] = R0[1]; rec[rank1][1] = R1[1]; rec[rank1][2] = R2[1]; }

    const int countPad = (count + 3) & ~3;
    for (int t2 = count + tid; t2 < countPad; t2 += NT) {
        rec[t2][0] = make_float4(0.f, 0.f, 0.f, 0.f);
        rec[t2][1] = make_float4(0.f, 0.f, 0.f, 0.f);
        rec[t2][2] = make_float4(0.f, __uint_as_float(0xFFFFu),
                                 __uint_as_float(0xFFFFu), 0.f);
    }
    __syncthreads();

    // ---------------- phase 4: composite, 1 px/thread ----------------
    const int pxi = tileX + (tid & (TW - 1));
    const int pyi = tileY + (tid >> 4);
    const float pxf = (float)pxi;
    const float pyf = (float)pyi;

    float T = 1.0f, rr = 0.0f, gg = 0.0f, bb = 0.0f;
    for (int base = 0; base < countPad; base += 4) {
        float4 q0[4], q1[4], q2[4];
        #pragma unroll
        for (int i = 0; i < 4; i++) {
            q0[i] = rec[base+i][0];
            q1[i] = rec[base+i][1];
            q2[i] = rec[base+i][2];
        }
        float gs[4];
        #pragma unroll
        for (int i = 0; i < 4; i++) {
            const unsigned lo = __float_as_uint(q2[i].y);
            const unsigned hi = __float_as_uint(q2[i].z);
            const int x0 = (int)(lo & 0xffffu), x1 = (int)(lo >> 16);
            const int y0 = (int)(hi & 0xffffu), y1 = (int)(hi >> 16);
            const bool inb = (pxi >= x0) & (pxi < x1) & (pyi >= y0) & (pyi < y1);
            const float dx = pxf - q0[i].x;
            const float dy = pyf - q0[i].y;
            const float u  = fmaf(q1[i].x * dy, dy, q1[i].y);   // e11*dy^2 + bias
            const float pl = fmaf(q0[i].w, dy, q0[i].z * dx);   // e01*dy + e00*dx
            const float e  = fmaf(pl, dx, u);
            gs[i] = inb ? ex2(e) : 0.0f;                        // alpha
        }
        #pragma unroll
        for (int i = 0; i < 4; i++) {
            const float tg = T * gs[i];
            rr = fmaf(tg, q1[i].z, rr);
            gg = fmaf(tg, q1[i].w, gg);
            bb = fmaf(tg, q2[i].x, bb);
            T  = T - tg;
        }
        if (T < 1e-5f) break;
    }

    const int idx = (pyi * IMG + pxi) * 3;
    out[idx + 0] = rr;
    out[idx + 1] = gg;
    out[idx + 2] = bb;
}

extern "C" void kernel_launch(void* const* d_in, const int* in_sizes, int n_in,
                              void* d_out, int out_size)
{
    const float* pos   = (const float*)d_in[0];  // (512,3)
    const float* cov3d = (const float*)d_in[1];  // (512,3,3)
    const float* opac  = (const float*)d_in[2];  // (512,1)
    const float* cols  = (const float*)d_in[3];  // (512,3)
    const float* Km    = (const float*)d_in[4];  // (3,3)
    const float* Rm    = (const float*)d_in[5];  // (3,3)
    const float* tv    = (const float*)d_in[6];  // (3,)
    float* out = (float*)d_out;                  // (256,256,3)

    gs_project<<<4, 128>>>(pos, cov3d, opac, cols, Km, Rm, tv);
    gs_raster<<<dim3(IMG/TW, IMG/TH), NT>>>(out);
}